// round 6
// baseline (speedup 1.0000x reference)
#include <cuda_runtime.h>
#include <cstdint>

#define BATCH 64
#define NB    64
#define RANK  4
#define SEQ   4096

// sqrt(log2(e)) — folds natural-exp into a single ex2.approx
#define SQRT_LOG2E 1.2011224087864498f

#define KS1 4    // split-K, layer 1
#define KS2 8    // split-K, layer 2
#define KS3 8    // split-K, layer 3
#define OMSZ (BATCH * NB * RANK * 2)   // floats per omega partial (32768)

// ---------------------------------------------------------------------------
// Scratch (device globals; no allocation allowed)
// ---------------------------------------------------------------------------
__device__ float g_h1p[KS1 * BATCH * 512];     // pre-relu partials of layer 1
__device__ float g_h2p[KS2 * BATCH * 1024];    // pre-relu partials of layer 2
__device__ float g_om [KS3 * OMSZ];            // packed omega partials
// omega packing within one partial: [((b*NB+n)*RANK+r)*2 + side]

// ---------------------------------------------------------------------------
// Tiled GEMM, PDL-aware: W-staging threads issue their first loads BEFORE
// cudaGridDependencySynchronize(); only the A-path (predecessor output)
// loads after it. Depth-2 register prefetch over 8-k smem chunks (load c+2
// while computing c), double-buffered smem, one barrier per chunk.
// Block tile = 64 batch rows x 64 cols; 256 threads = 16 tx (4 cols) x
// 16 ty (4 rows); accumulators = 8 packed f32x2 (col pairs).
// Split-K via blockIdx.z -> disjoint partials (bias only in split 0);
// A-staging threads sum the producer's NPART partials (+relu) inline.
// SRC: 0 = Ain param (no relu, no gridsync), 1 = g_h1p, 2 = g_h2p
// DST: 0 = g_h1p partial, 1 = g_h2p partial, 2 = packed omega partial
// ---------------------------------------------------------------------------
template <int K, int N, int KS, int SRC, int NPART, int DST>
__global__ __launch_bounds__(256)
void gemm_tiled(const float* __restrict__ Ain,
                const float* __restrict__ W,
                const float* __restrict__ bias)
{
    constexpr int KC  = K / KS;     // k-range per block
    constexpr int NCH = KC / 8;     // 8-k chunks

    __shared__ __align__(16) float sW[2][8][64];   // [buf][kk][col]
    __shared__ __align__(16) float sA[2][8][64];   // [buf][kk][b]

    const int tid = threadIdx.x;
    const int tx  = tid & 15;          // col quad
    const int ty  = tid >> 4;          // row quad
    const int j0  = blockIdx.x * 64;
    const int z   = blockIdx.z;
    const int k0  = z * KC;

    const bool isW = tid < 128;
    const int w_kk = tid >> 4;             // valid if isW
    const int w_c4 = (tid & 15) * 4;
    const int a_i  = tid - 128;
    const int a_b  = a_i >> 1;
    const int a_kq = (a_i & 1) * 4;

    auto load_W = [&](int kc) -> float4 {
        return *reinterpret_cast<const float4*>(
            W + (size_t)(k0 + kc + w_kk) * N + j0 + w_c4);
    };
    auto load_A = [&](int kc) -> float4 {
        float4 av;
        if (SRC == 0) {
            av = *reinterpret_cast<const float4*>(Ain + a_b * K + k0 + kc + a_kq);
        } else {
            const float* base = (SRC == 1) ? g_h1p : g_h2p;
            const float* p0 = base + a_b * K + k0 + kc + a_kq;
            av = *reinterpret_cast<const float4*>(p0);
            #pragma unroll
            for (int p = 1; p < NPART; p++) {
                const float4 pv = *reinterpret_cast<const float4*>(p0 + p * (BATCH * K));
                av.x += pv.x; av.y += pv.y; av.z += pv.z; av.w += pv.w;
            }
            av.x = fmaxf(av.x, 0.f); av.y = fmaxf(av.y, 0.f);
            av.z = fmaxf(av.z, 0.f); av.w = fmaxf(av.w, 0.f);
        }
        return av;
    };
    auto load_chunk = [&](int kc) -> float4 {
        return isW ? load_W(kc) : load_A(kc);
    };
    auto store_chunk = [&](int buf, float4 v) {
        if (isW) {
            *reinterpret_cast<float4*>(&sW[buf][w_kk][w_c4]) = v;
        } else {
            sA[buf][a_kq + 0][a_b] = v.x;
            sA[buf][a_kq + 1][a_b] = v.y;
            sA[buf][a_kq + 2][a_b] = v.z;
            sA[buf][a_kq + 3][a_b] = v.w;
        }
    };

    unsigned long long acc2[4][2];   // [row r][col pair]
    #pragma unroll
    for (int r = 0; r < 4; r++) { acc2[r][0] = 0ull; acc2[r][1] = 0ull; }

    // ---- PDL prologue: W loads fly before the dependency sync ----
    float4 r0;
    if (isW) r0 = load_W(0);
#if __CUDA_ARCH__ >= 900
    if (SRC != 0) cudaGridDependencySynchronize();
#endif
    if (!isW) r0 = load_A(0);
    store_chunk(0, r0);
    float4 r1;
    if (NCH > 1) r1 = load_chunk(8);
    __syncthreads();

    for (int c = 0; c < NCH; c++) {
        float4 r2;
        if (c + 2 < NCH) r2 = load_chunk((c + 2) * 8);

        const int buf = c & 1;
        #pragma unroll
        for (int kk = 0; kk < 8; kk++) {
            const ulonglong2 wq =
                *reinterpret_cast<const ulonglong2*>(&sW[buf][kk][tx * 4]);
            const float4 av = *reinterpret_cast<const float4*>(&sA[buf][kk][ty * 4]);
            const float aa[4] = {av.x, av.y, av.z, av.w};
            #pragma unroll
            for (int r = 0; r < 4; r++) {
                unsigned long long ap;
                asm("mov.b64 %0, {%1, %1};" : "=l"(ap) : "f"(aa[r]));
                asm("fma.rn.f32x2 %0, %1, %2, %0;"
                    : "+l"(acc2[r][0]) : "l"(ap), "l"(wq.x));
                asm("fma.rn.f32x2 %0, %1, %2, %0;"
                    : "+l"(acc2[r][1]) : "l"(ap), "l"(wq.y));
            }
        }

        if (c + 1 < NCH) store_chunk((c + 1) & 1, r1);
        __syncthreads();
        r1 = r2;
    }

    // ---- epilogue ----
    float o[4][4];
    #pragma unroll
    for (int r = 0; r < 4; r++) {
        asm("mov.b64 {%0, %1}, %2;" : "=f"(o[r][0]), "=f"(o[r][1]) : "l"(acc2[r][0]));
        asm("mov.b64 {%0, %1}, %2;" : "=f"(o[r][2]), "=f"(o[r][3]) : "l"(acc2[r][1]));
    }
    const int j = j0 + tx * 4;
    if (z == 0) {
        const float4 bv = *reinterpret_cast<const float4*>(bias + j);
        #pragma unroll
        for (int r = 0; r < 4; r++) {
            o[r][0] += bv.x; o[r][1] += bv.y; o[r][2] += bv.z; o[r][3] += bv.w;
        }
    }
    #pragma unroll
    for (int r = 0; r < 4; r++) {
        const int b = ty * 4 + r;
        if (DST == 0) {
            *reinterpret_cast<float4*>(g_h1p + z * (BATCH * 512) + b * 512 + j) =
                make_float4(o[r][0], o[r][1], o[r][2], o[r][3]);
        } else if (DST == 1) {
            *reinterpret_cast<float4*>(g_h2p + z * (BATCH * 1024) + b * 1024 + j) =
                make_float4(o[r][0], o[r][1], o[r][2], o[r][3]);
        } else {
            const int side = (j >= 256) ? 1 : 0;
            const int n    = (j - side * 256) >> 2;   // basis index; cols = ranks
            float* dst = g_om + z * OMSZ + ((b * NB + n) * RANK) * 2 + side;
            dst[0] = o[r][0]; dst[2] = o[r][1];
            dst[4] = o[r][2]; dst[6] = o[r][3];
        }
    }
}

// ---------------------------------------------------------------------------
// Basis + rank-4 projection. grid(SEQ/128, BATCH) = 2048 blocks of 128
// threads, 1 point/thread (max occupancy; LDS per point stays within the L1
// budget). PDL: t + basis-param loads are issued before the dependency sync;
// only the omega partial reads wait. Per (point, n): ex2.approx + cos.approx
// + 4 fma-pipe ops + 1 pack + 4 fma.rn.f32x2.
// ---------------------------------------------------------------------------
__global__ __launch_bounds__(128)
void basis_kernel(const float* __restrict__ t,
                  const float* __restrict__ mu,
                  const float* __restrict__ alpha,
                  const float* __restrict__ beta,
                  const float* __restrict__ gamma,
                  float* __restrict__ out)
{
    __shared__ __align__(16) float4 s_bp[NB];        // (a2, -a2*mu, beta, gamma)
    __shared__ __align__(16) float2 s_om[NB * RANK]; // (even, odd) per (n, r)

    const int tid = threadIdx.x;
    const int b   = blockIdx.y;
    const int s   = blockIdx.x * 128 + tid;

    // -- independent loads before the dependency sync --
    const float tv = t[(size_t)b * SEQ + s];
    float p_al = 0.f, p_mu = 0.f, p_be = 0.f, p_ga = 0.f;
    if (tid < NB) {
        p_al = alpha[tid]; p_mu = mu[tid]; p_be = beta[tid]; p_ga = gamma[tid];
    }

#if __CUDA_ARCH__ >= 900
    cudaGridDependencySynchronize();
#endif

    if (tid < NB) {
        const float a2 = p_al * SQRT_LOG2E;
        s_bp[tid] = make_float4(a2, -a2 * p_mu, p_be, p_ga);
    }
    {
        // 128 float4 = 512 floats of omega; each thread sums KS3 partials of one
        const float4* src = reinterpret_cast<const float4*>(g_om + b * (NB * RANK * 2));
        float4 acc = src[tid];
        #pragma unroll
        for (int p = 1; p < KS3; p++) {
            const float4 pv = src[p * (OMSZ / 4) + tid];
            acc.x += pv.x; acc.y += pv.y; acc.z += pv.z; acc.w += pv.w;
        }
        reinterpret_cast<float4*>(s_om)[tid] = acc;
    }
    __syncthreads();

    unsigned long long acc[RANK];
    #pragma unroll
    for (int r = 0; r < RANK; r++) acc[r] = 0ull;

    const unsigned long long* omq =
        reinterpret_cast<const unsigned long long*>(s_om);

    #pragma unroll 4
    for (int n = 0; n < NB; n++) {
        const float4 bp = s_bp[n];
        const ulonglong2 q0 = *reinterpret_cast<const ulonglong2*>(omq + n * 4);
        const ulonglong2 q1 = *reinterpret_cast<const ulonglong2*>(omq + n * 4 + 2);

        const float u  = fmaf(bp.x, tv, bp.y);   // sqrt(log2e)*alpha*(t-mu)
        const float nv = -u * u;
        float e;
        asm("ex2.approx.f32 %0, %1;" : "=f"(e) : "f"(nv));
        const float w = fmaf(bp.z, tv, bp.w);    // beta*t + gamma
        float c;
        asm("cos.approx.f32 %0, %1;" : "=f"(c) : "f"(w));
        const float pr = e * c;                  // h_t[b,s,n]
        unsigned long long pp;
        asm("mov.b64 %0, {%1, %1};" : "=l"(pp) : "f"(pr));
        asm("fma.rn.f32x2 %0, %1, %2, %0;" : "+l"(acc[0]) : "l"(pp), "l"(q0.x));
        asm("fma.rn.f32x2 %0, %1, %2, %0;" : "+l"(acc[1]) : "l"(pp), "l"(q0.y));
        asm("fma.rn.f32x2 %0, %1, %2, %0;" : "+l"(acc[2]) : "l"(pp), "l"(q1.x));
        asm("fma.rn.f32x2 %0, %1, %2, %0;" : "+l"(acc[3]) : "l"(pp), "l"(q1.y));
    }

    float ev[4], od[4];
    #pragma unroll
    for (int r = 0; r < RANK; r++)
        asm("mov.b64 {%0, %1}, %2;" : "=f"(ev[r]), "=f"(od[r]) : "l"(acc[r]));
    float4* op = reinterpret_cast<float4*>(
        out + (size_t)b * (2 * SEQ * RANK) + (size_t)s * 8);
    op[0] = make_float4(ev[0], ev[1], ev[2], ev[3]);   // row 2s
    op[1] = make_float4(od[0], od[1], od[2], od[3]);   // row 2s+1
}

// ---------------------------------------------------------------------------
// Launch (PDL-chained via cudaLaunchKernelEx)
// ---------------------------------------------------------------------------
template <typename Kern, typename... Args>
static void launch_pdl(Kern k, dim3 grid, dim3 blk, bool pdl, Args... args)
{
    cudaLaunchConfig_t cfg = {};
    cfg.gridDim = grid;
    cfg.blockDim = blk;
    cfg.stream = 0;
    cudaLaunchAttribute at[1];
    if (pdl) {
        at[0].id = cudaLaunchAttributeProgrammaticStreamSerialization;
        at[0].val.programmaticStreamSerializationAllowed = 1;
        cfg.attrs = at;
        cfg.numAttrs = 1;
    }
    cudaLaunchKernelEx(&cfg, k, args...);
}

extern "C" void kernel_launch(void* const* d_in, const int* in_sizes, int n_in,
                              void* d_out, int out_size)
{
    const float* f     = (const float*)d_in[0];
    const float* t     = (const float*)d_in[1];
    const float* W1    = (const float*)d_in[2];
    const float* b1    = (const float*)d_in[3];
    const float* W2    = (const float*)d_in[4];
    const float* b2    = (const float*)d_in[5];
    const float* W3    = (const float*)d_in[6];
    const float* b3    = (const float*)d_in[7];
    const float* mu    = (const float*)d_in[8];
    const float* alpha = (const float*)d_in[9];
    const float* beta  = (const float*)d_in[10];
    const float* gamma = (const float*)d_in[11];
    float* out = (float*)d_out;

    // h1 partials = f @ W1 (+b1 in split 0)               [KS1][64, 512]
    launch_pdl(gemm_tiled<128, 512, KS1, 0, 1, 0>,
               dim3(8, 1, KS1), dim3(256), false, f, W1, b1);
    // h2 partials = relu(sum h1p) @ W2 (+b2 in split 0)   [KS2][64, 1024]
    launch_pdl(gemm_tiled<512, 1024, KS2, 1, KS1, 1>,
               dim3(16, 1, KS2), dim3(256), true, (const float*)nullptr, W2, b2);
    // omega partials = relu(sum h2p) @ W3 (+b3)           [KS3][64, 512] packed
    launch_pdl(gemm_tiled<1024, 512, KS3, 2, KS2, 2>,
               dim3(8, 1, KS3), dim3(256), true, (const float*)nullptr, W3, b3);
    // basis + projection
    launch_pdl(basis_kernel, dim3(SEQ / 128, BATCH), dim3(128), true,
               t, mu, alpha, beta, gamma, out);
}